// round 5
// baseline (speedup 1.0000x reference)
#include <cuda_runtime.h>
#include <math.h>
#include <stdint.h>

// ---------------- problem constants ----------------
#define BATCH   8
#define CH      256
#define HH      64
#define WW      64
#define HWSZ    (HH*WW)          // 4096
#define NTOK    (BATCH*HWSZ)     // 32768
#define HID     1024
#define NHEAD   8
#define HDIM    32

// ---------------- scratch ----------------
__device__ float g_ts[NTOK*CH];    // sub transposed [tok][c] (tf32)
__device__ float g_to[NTOK*CH];    // ori transposed [tok][c] (tf32)
__device__ float g_q [BATCH*CH*HWSZ];   // channel-major
__device__ float g_k [BATCH*CH*HWSZ];
__device__ float g_v [BATCH*CH*HWSZ];
__device__ float g_x [NTOK*CH];    // attention out (tf32), [tok,256]
__device__ float g_xp[NTOK*CH];    // proj out fp32 (residual)
__device__ float g_ln[NTOK*CH];    // layernorm out (tf32)
__device__ float g_h [NTOK*HID];   // mlp hidden (tf32)
__device__ float g_wq [CH*CH];     // tf32-rounded weights
__device__ float g_wkv[2*CH*CH];   // wk rows 0..255, wv rows 256..511
__device__ float g_wp [CH*CH];
__device__ float g_w1 [HID*CH];
__device__ float g_w2 [CH*HID];

// ---------------- helpers ----------------
__device__ __forceinline__ float cvtf(float x) {
    unsigned u;
    asm("cvt.rna.tf32.f32 %0, %1;" : "=r"(u) : "f"(x));
    return __uint_as_float(u);
}
__device__ __forceinline__ uint32_t smem_u32(const void* p) {
    uint32_t a;
    asm("{ .reg .u64 t; cvta.to.shared.u64 t, %1; cvt.u32.u64 %0, t; }"
        : "=r"(a) : "l"(p));
    return a;
}
__device__ __forceinline__ void cp16(uint32_t s, const void* g) {
    asm volatile("cp.async.cg.shared.global [%0], [%1], 16;" :: "r"(s), "l"(g));
}
#define CP_COMMIT() asm volatile("cp.async.commit_group;" ::: "memory")
#define CP_WAIT2()  asm volatile("cp.async.wait_group 2;" ::: "memory")

__device__ __forceinline__ void ldsm_x4(uint32_t r[4], uint32_t addr) {
    asm volatile("ldmatrix.sync.aligned.m8n8.x4.shared.b16 {%0,%1,%2,%3}, [%4];"
        : "=r"(r[0]), "=r"(r[1]), "=r"(r[2]), "=r"(r[3]) : "r"(addr));
}
__device__ __forceinline__ void mma_tf32(float c[4], const uint32_t a[4],
                                         uint32_t b0, uint32_t b1) {
    asm volatile(
        "mma.sync.aligned.m16n8k8.row.col.f32.tf32.tf32.f32 "
        "{%0,%1,%2,%3}, {%4,%5,%6,%7}, {%8,%9}, {%0,%1,%2,%3};\n"
        : "+f"(c[0]), "+f"(c[1]), "+f"(c[2]), "+f"(c[3])
        : "r"(a[0]), "r"(a[1]), "r"(a[2]), "r"(a[3]), "r"(b0), "r"(b1));
}

// =====================================================================
// Wide tf32 NT GEMM: C[m,n] = sum_k A[m,k] * W[n,k] + epilogue
// CTA tile 128(m) x 256(n), 512 threads (16 warps, warp = 32x64),
// K-chunk 32, 3-stage cp.async, ldmatrix fragments, SW-swizzled smem.
// MODE 4 (Q):      transposed store to out1[B][CH][HWSZ], no bias
// MODE 5 (KV):     n<256 -> out1 (k), n>=256 -> out2 (v); transposed, no bias
// MODE 6 (PROJLN): +bias -> out1 (xp fp32) AND fused LayerNorm -> out2 (ln, tf32)
// MODE 1 (FC1):    +bias, exact GELU, cvtf -> out1[m][HID]
// MODE 2 (FC2):    +bias +resid(out2)[m][n], transposed store out1[B][CH][HWSZ]
// =====================================================================
#define TM 128
#define TN 256
#define STAGE_B 49152          // 16KB A + 32KB B
#define SMEM_SZ (3*STAGE_B)    // 147456

template<int MODE, int KDIM>
__global__ __launch_bounds__(512, 1)
void gemm_wide(const float* __restrict__ A, const float* __restrict__ Wt,
               const float* __restrict__ bias,
               float* __restrict__ out1, float* __restrict__ out2,
               const float* __restrict__ lnw, const float* __restrict__ lnb)
{
    constexpr int LDC = (MODE == 1) ? HID : CH;
    extern __shared__ __align__(128) char smem[];
    __shared__ float s_sum[4][TM];
    __shared__ float s_sq [4][TM];
    const uint32_t sb = smem_u32(smem);

    const int tid  = threadIdx.x;
    const int lane = tid & 31;
    const int wid  = tid >> 5;
    const int wm   = wid & 3;      // m: 32-row block (0..3)
    const int wn   = wid >> 2;     // n: 64-col block (0..3)
    const int lq   = lane >> 2;
    const int lr   = lane & 3;

    const int nT = blockIdx.x * TN;
    const int mT = blockIdx.y * TM;
    const int NCH = KDIM / 32;

    // ldmatrix per-thread rows (identical math to proven round-4 kernel)
    const int arow  = wm * 32 + (lane & 15);
    const int aqsel = lane >> 4;
    const uint32_t abase0 = (uint32_t)arow * 128;
    const uint32_t abase1 = (uint32_t)(arow + 16) * 128;
    const int axor = arow & 7;
    const int brow  = wn * 64 + (lane & 7) + ((lane >> 4) << 3);
    const int bqsel = (lane >> 3) & 1;

    float acc[2][8][4];
    #pragma unroll
    for (int i = 0; i < 2; i++)
        #pragma unroll
        for (int j = 0; j < 8; j++)
            #pragma unroll
            for (int u = 0; u < 4; u++) acc[i][j][u] = 0.f;

    auto load_stage = [&](int s, int kt) {
        const uint32_t ab = sb + s * STAGE_B;
        const uint32_t bbm = ab + 16384;
        #pragma unroll
        for (int j = 0; j < 2; j++) {                 // A: 128 rows x 8 q16
            int c = tid + j * 512;
            int row = c >> 3, q = c & 7;
            uint32_t off = (uint32_t)row * 128 + (uint32_t)((q ^ (row & 7)) * 16);
            cp16(ab + off, A + (size_t)(mT + row) * KDIM + kt + q * 4);
        }
        #pragma unroll
        for (int j = 0; j < 4; j++) {                 // B: 256 rows x 8 q16
            int c = tid + j * 512;
            int row = c >> 3, q = c & 7;
            uint32_t off = (uint32_t)row * 128 + (uint32_t)((q ^ (row & 7)) * 16);
            cp16(bbm + off, Wt + (size_t)(nT + row) * KDIM + kt + q * 4);
        }
    };

    load_stage(0, 0);  CP_COMMIT();
    load_stage(1, 32); CP_COMMIT();
    load_stage(2, 64); CP_COMMIT();

    for (int it = 0; it < NCH; it++) {
        const int s = it % 3;
        CP_WAIT2();
        __syncthreads();

        const uint32_t ab = sb + s * STAGE_B;
        const uint32_t bbm = ab + 16384;

        #pragma unroll
        for (int kk = 0; kk < 4; kk++) {
            const int q0 = kk * 2;
            uint32_t af[2][4];
            {
                const int qa = q0 + aqsel;
                ldsm_x4(af[0], ab + abase0 + (uint32_t)((qa ^ axor) * 16));
                ldsm_x4(af[1], ab + abase1 + (uint32_t)((qa ^ axor) * 16));
            }
            #pragma unroll
            for (int nt2 = 0; nt2 < 4; nt2++) {
                const int row = brow + nt2 * 16;
                const int qb = q0 + bqsel;
                uint32_t bf[4];
                ldsm_x4(bf, bbm + (uint32_t)row * 128 + (uint32_t)((qb ^ (row & 7)) * 16));
                mma_tf32(acc[0][nt2*2  ], af[0], bf[0], bf[1]);
                mma_tf32(acc[0][nt2*2+1], af[0], bf[2], bf[3]);
                mma_tf32(acc[1][nt2*2  ], af[1], bf[0], bf[1]);
                mma_tf32(acc[1][nt2*2+1], af[1], bf[2], bf[3]);
            }
        }
        __syncthreads();
        if (it + 3 < NCH) load_stage(s, (it + 3) * 32);
        CP_COMMIT();
    }

    // ---------------- epilogue ----------------
    if (MODE == 4 || MODE == 5) {
        // transposed store to channel-major buffers, no bias
        #pragma unroll
        for (int mt = 0; mt < 2; mt++) {
            #pragma unroll
            for (int idx = 0; idx < 8; idx++) {
                const int nt2 = idx >> 1, tt = idx & 1;
                const int m0 = mT + wm * 32 + mt * 16 + lq;
                const int n0 = nT + wn * 64 + nt2 * 16 + tt * 8 + (lr << 1);
                const float* cc = acc[mt][idx];
                const int bi = m0 >> 12;
                const int hw = m0 & 4095;
                float* dst;
                int ch;
                if (MODE == 5) { dst = (n0 < CH) ? out1 : out2; ch = n0 & (CH - 1); }
                else           { dst = out1; ch = n0; }
                float* p = dst + (size_t)bi * CH * HWSZ;
                p[(size_t)(ch    ) * HWSZ + hw    ] = cc[0];
                p[(size_t)(ch + 1) * HWSZ + hw    ] = cc[1];
                p[(size_t)(ch    ) * HWSZ + hw + 8] = cc[2];
                p[(size_t)(ch + 1) * HWSZ + hw + 8] = cc[3];
            }
        }
    } else if (MODE == 1) {
        #pragma unroll
        for (int mt = 0; mt < 2; mt++) {
            #pragma unroll
            for (int idx = 0; idx < 8; idx++) {
                const int nt2 = idx >> 1, tt = idx & 1;
                const int m0 = mT + wm * 32 + mt * 16 + lq;
                const int n0 = nT + wn * 64 + nt2 * 16 + tt * 8 + (lr << 1);
                const float* cc = acc[mt][idx];
                float2 bv = *(const float2*)&bias[n0];
                float v[4] = {cc[0] + bv.x, cc[1] + bv.y, cc[2] + bv.x, cc[3] + bv.y};
                #pragma unroll
                for (int u = 0; u < 4; u++)
                    v[u] = cvtf(0.5f * v[u] * (1.f + erff(v[u] * 0.70710678118654752f)));
                *(float2*)&out1[(size_t)m0 * LDC + n0]       = make_float2(v[0], v[1]);
                *(float2*)&out1[(size_t)(m0 + 8) * LDC + n0] = make_float2(v[2], v[3]);
            }
        }
    } else if (MODE == 2) {
        const float* resid = out2;
        #pragma unroll
        for (int mt = 0; mt < 2; mt++) {
            #pragma unroll
            for (int idx = 0; idx < 8; idx++) {
                const int nt2 = idx >> 1, tt = idx & 1;
                const int m0 = mT + wm * 32 + mt * 16 + lq;
                const int n0 = nT + wn * 64 + nt2 * 16 + tt * 8 + (lr << 1);
                const float* cc = acc[mt][idx];
                float2 bv = *(const float2*)&bias[n0];
                float2 r0 = *(const float2*)&resid[(size_t)m0 * CH + n0];
                float2 r1 = *(const float2*)&resid[(size_t)(m0 + 8) * CH + n0];
                const int bi = m0 >> 12;
                const int hw = m0 & 4095;
                float* p = out1 + (size_t)bi * CH * HWSZ;
                p[(size_t)(n0    ) * HWSZ + hw    ] = cc[0] + bv.x + r0.x;
                p[(size_t)(n0 + 1) * HWSZ + hw    ] = cc[1] + bv.y + r0.y;
                p[(size_t)(n0    ) * HWSZ + hw + 8] = cc[2] + bv.x + r1.x;
                p[(size_t)(n0 + 1) * HWSZ + hw + 8] = cc[3] + bv.y + r1.y;
            }
        }
    } else {
        // MODE 6: proj + bias -> xp (out1), fused LayerNorm -> ln (out2)
        // 1) add bias in place, store xp
        #pragma unroll
        for (int mt = 0; mt < 2; mt++) {
            #pragma unroll
            for (int idx = 0; idx < 8; idx++) {
                const int nt2 = idx >> 1, tt = idx & 1;
                const int m0 = mT + wm * 32 + mt * 16 + lq;
                const int n0 = wn * 64 + nt2 * 16 + tt * 8 + (lr << 1);  // nT==0
                float* cc = acc[mt][idx];
                float2 bv = *(const float2*)&bias[n0];
                cc[0] += bv.x; cc[1] += bv.y; cc[2] += bv.x; cc[3] += bv.y;
                *(float2*)&out1[(size_t)m0 * CH + n0]       = make_float2(cc[0], cc[1]);
                *(float2*)&out1[(size_t)(m0 + 8) * CH + n0] = make_float2(cc[2], cc[3]);
            }
        }
        // 2) per-thread partials: 4 rows (mt x {lq, lq+8}), 16 cols each
        float ps[4] = {0, 0, 0, 0}, pq[4] = {0, 0, 0, 0};
        #pragma unroll
        for (int mt = 0; mt < 2; mt++)
            #pragma unroll
            for (int idx = 0; idx < 8; idx++) {
                const float* cc = acc[mt][idx];
                ps[mt*2  ] += cc[0] + cc[1];
                pq[mt*2  ] += cc[0]*cc[0] + cc[1]*cc[1];
                ps[mt*2+1] += cc[2] + cc[3];
                pq[mt*2+1] += cc[2]*cc[2] + cc[3]*cc[3];
            }
        // 3) quad reduce over lr
        #pragma unroll
        for (int o = 1; o <= 2; o <<= 1)
            #pragma unroll
            for (int r = 0; r < 4; r++) {
                ps[r] += __shfl_xor_sync(0xffffffffu, ps[r], o);
                pq[r] += __shfl_xor_sync(0xffffffffu, pq[r], o);
            }
        if (lr == 0) {
            #pragma unroll
            for (int r = 0; r < 4; r++) {
                const int row = wm * 32 + (r >> 1) * 16 + lq + (r & 1) * 8;
                s_sum[wn][row] = ps[r];
                s_sq [wn][row] = pq[r];
            }
        }
        __syncthreads();
        // 4) mean / inv-std for this thread's 4 rows
        float mean[4], inv[4];
        #pragma unroll
        for (int r = 0; r < 4; r++) {
            const int row = wm * 32 + (r >> 1) * 16 + lq + (r & 1) * 8;
            float s = s_sum[0][row] + s_sum[1][row] + s_sum[2][row] + s_sum[3][row];
            float q = s_sq [0][row] + s_sq [1][row] + s_sq [2][row] + s_sq [3][row];
            mean[r] = s * (1.f / 256.f);
            float var = q * (1.f / 256.f) - mean[r] * mean[r];
            inv[r] = rsqrtf(var + 1e-5f);
        }
        // 5) normalized store (tf32-rounded)
        #pragma unroll
        for (int mt = 0; mt < 2; mt++) {
            #pragma unroll
            for (int idx = 0; idx < 8; idx++) {
                const int nt2 = idx >> 1, tt = idx & 1;
                const int m0 = mT + wm * 32 + mt * 16 + lq;
                const int n0 = wn * 64 + nt2 * 16 + tt * 8 + (lr << 1);
                const float* cc = acc[mt][idx];
                float2 lw = *(const float2*)&lnw[n0];
                float2 lb = *(const float2*)&lnb[n0];
                const int r0 = mt * 2, r1 = mt * 2 + 1;
                float o0 = cvtf((cc[0] - mean[r0]) * inv[r0] * lw.x + lb.x);
                float o1 = cvtf((cc[1] - mean[r0]) * inv[r0] * lw.y + lb.y);
                float o2 = cvtf((cc[2] - mean[r1]) * inv[r1] * lw.x + lb.x);
                float o3 = cvtf((cc[3] - mean[r1]) * inv[r1] * lw.y + lb.y);
                *(float2*)&out2[(size_t)m0 * CH + n0]       = make_float2(o0, o1);
                *(float2*)&out2[(size_t)(m0 + 8) * CH + n0] = make_float2(o2, o3);
            }
        }
    }
}

// =====================================================================
// Tiled transpose + tf32 round: [b][256][4096] -> [b*4096][256]
// =====================================================================
__global__ void transpose_cvt(const float* __restrict__ in, float* __restrict__ out)
{
    __shared__ float t[32][33];
    const int b  = blockIdx.z;
    const int p0 = blockIdx.x * 32;
    const int c0 = blockIdx.y * 32;
    const int tx = threadIdx.x, ty = threadIdx.y;   // 32 x 8
    const float* ib = in + (size_t)b * CH * HWSZ;
    float* ob = out + (size_t)b * HWSZ * CH;
    #pragma unroll
    for (int i = 0; i < 4; i++)
        t[ty + 8*i][tx] = ib[(size_t)(c0 + ty + 8*i) * HWSZ + p0 + tx];
    __syncthreads();
    #pragma unroll
    for (int i = 0; i < 4; i++)
        ob[(size_t)(p0 + ty + 8*i) * CH + c0 + tx] = cvtf(t[tx][ty + 8*i]);
}

// =====================================================================
// Dilated 3x3 local attention. 1 thread = (pixel, head). Channel-major.
// =====================================================================
__global__ void attn_kernel(const float* __restrict__ q,
                            const float* __restrict__ k,
                            const float* __restrict__ v,
                            float* __restrict__ xo)
{
    const int b    = blockIdx.z;
    const int head = blockIdx.y;
    const int n    = blockIdx.x * 128 + threadIdx.x;
    const int py   = n >> 6;
    const int px   = n & 63;
    const int dil  = (head >> 1) + 1;

    const size_t base = ((size_t)b * CH + head * HDIM) * HWSZ;
    const float* qb = q + base + n;
    const float* kb = k + base;
    const float* vb = v + base;

    float qr[HDIM];
    #pragma unroll
    for (int c = 0; c < HDIM; c++) qr[c] = qb[(size_t)c * HWSZ];

    int nn[9];
    #pragma unroll
    for (int t = 0; t < 9; t++) {
        int yy = py + (t / 3 - 1) * dil;
        int xx = px + (t % 3 - 1) * dil;
        nn[t] = (yy >= 0 && yy < HH && xx >= 0 && xx < WW) ? (yy * WW + xx) : -1;
    }

    float logit[9];
    #pragma unroll
    for (int t = 0; t < 9; t++) {
        float acc = 0.f;
        if (nn[t] >= 0) {
            #pragma unroll
            for (int c = 0; c < HDIM; c++)
                acc += qr[c] * kb[(size_t)c * HWSZ + nn[t]];
        }
        logit[t] = acc * 0.17677669529663687f;
    }

    float mx = logit[0];
    #pragma unroll
    for (int t = 1; t < 9; t++) mx = fmaxf(mx, logit[t]);
    float s = 0.f;
    #pragma unroll
    for (int t = 0; t < 9; t++) { logit[t] = __expf(logit[t] - mx); s += logit[t]; }
    const float inv = 1.f / s;
    #pragma unroll
    for (int t = 0; t < 9; t++) logit[t] *= inv;

    float* xrow = xo + ((size_t)(b * HWSZ + n)) * CH + head * HDIM;
    #pragma unroll
    for (int c0 = 0; c0 < HDIM; c0 += 4) {
        float o[4];
        #pragma unroll
        for (int u = 0; u < 4; u++) {
            float acc = 0.f;
            #pragma unroll
            for (int t = 0; t < 9; t++)
                if (nn[t] >= 0)
                    acc += logit[t] * vb[(size_t)(c0 + u) * HWSZ + nn[t]];
            o[u] = cvtf(acc);
        }
        *(float4*)&xrow[c0] = make_float4(o[0], o[1], o[2], o[3]);
    }
}

// ---------------- weight pre-round (rna -> tf32) ----------------
__global__ void round_w(const float* __restrict__ a, float* __restrict__ b, int n)
{
    int i = blockIdx.x * 256 + threadIdx.x;
    if (i < n) b[i] = cvtf(a[i]);
}

// =====================================================================
extern "C" void kernel_launch(void* const* d_in, const int* in_sizes, int n_in,
                              void* d_out, int out_size)
{
    const float* sub    = (const float*)d_in[0];
    const float* ori    = (const float*)d_in[1];
    const float* wq     = (const float*)d_in[2];
    const float* wk     = (const float*)d_in[3];
    const float* wv     = (const float*)d_in[4];
    const float* proj_w = (const float*)d_in[5];
    const float* proj_b = (const float*)d_in[6];
    const float* ln_w   = (const float*)d_in[7];
    const float* ln_b   = (const float*)d_in[8];
    const float* fc1_w  = (const float*)d_in[9];
    const float* fc1_b  = (const float*)d_in[10];
    const float* fc2_w  = (const float*)d_in[11];
    const float* fc2_b  = (const float*)d_in[12];
    float* out = (float*)d_out;

    float *p_ts, *p_to, *p_q, *p_k, *p_v, *p_x, *p_xp, *p_ln, *p_h;
    float *p_wq, *p_wkv, *p_wp, *p_w1, *p_w2;
    cudaGetSymbolAddress((void**)&p_ts,  g_ts);
    cudaGetSymbolAddress((void**)&p_to,  g_to);
    cudaGetSymbolAddress((void**)&p_q,   g_q);
    cudaGetSymbolAddress((void**)&p_k,   g_k);
    cudaGetSymbolAddress((void**)&p_v,   g_v);
    cudaGetSymbolAddress((void**)&p_x,   g_x);
    cudaGetSymbolAddress((void**)&p_xp,  g_xp);
    cudaGetSymbolAddress((void**)&p_ln,  g_ln);
    cudaGetSymbolAddress((void**)&p_h,   g_h);
    cudaGetSymbolAddress((void**)&p_wq,  g_wq);
    cudaGetSymbolAddress((void**)&p_wkv, g_wkv);
    cudaGetSymbolAddress((void**)&p_wp,  g_wp);
    cudaGetSymbolAddress((void**)&p_w1,  g_w1);
    cudaGetSymbolAddress((void**)&p_w2,  g_w2);

    cudaFuncSetAttribute(gemm_wide<4, CH >, cudaFuncAttributeMaxDynamicSharedMemorySize, SMEM_SZ);
    cudaFuncSetAttribute(gemm_wide<5, CH >, cudaFuncAttributeMaxDynamicSharedMemorySize, SMEM_SZ);
    cudaFuncSetAttribute(gemm_wide<6, CH >, cudaFuncAttributeMaxDynamicSharedMemorySize, SMEM_SZ);
    cudaFuncSetAttribute(gemm_wide<1, CH >, cudaFuncAttributeMaxDynamicSharedMemorySize, SMEM_SZ);
    cudaFuncSetAttribute(gemm_wide<2, HID>, cudaFuncAttributeMaxDynamicSharedMemorySize, SMEM_SZ);

    // weight pre-rounding (k,v stacked into g_wkv)
    round_w<<<(CH*CH  + 255) / 256, 256>>>(wq,     p_wq,          CH*CH);
    round_w<<<(CH*CH  + 255) / 256, 256>>>(wk,     p_wkv,         CH*CH);
    round_w<<<(CH*CH  + 255) / 256, 256>>>(wv,     p_wkv + CH*CH, CH*CH);
    round_w<<<(CH*CH  + 255) / 256, 256>>>(proj_w, p_wp,          CH*CH);
    round_w<<<(HID*CH + 255) / 256, 256>>>(fc1_w,  p_w1,          HID*CH);
    round_w<<<(CH*HID + 255) / 256, 256>>>(fc2_w,  p_w2,          CH*HID);

    // transpose inputs to [tok][c] with tf32 rounding
    dim3 gt(HWSZ / 32, CH / 32, BATCH);
    dim3 bt(32, 8);
    transpose_cvt<<<gt, bt>>>(sub, p_ts);
    transpose_cvt<<<gt, bt>>>(ori, p_to);

    // q (N=256) and stacked k|v (N=512), channel-major outputs
    dim3 gq(1, NTOK / TM);
    gemm_wide<4, CH><<<gq, 512, SMEM_SZ>>>(p_ts, p_wq, nullptr, p_q, nullptr, nullptr, nullptr);
    dim3 gkv(2, NTOK / TM);
    gemm_wide<5, CH><<<gkv, 512, SMEM_SZ>>>(p_to, p_wkv, nullptr, p_k, p_v, nullptr, nullptr);

    // attention -> g_x [tok][256] (tf32)
    dim3 ga(HWSZ / 128, NHEAD, BATCH);
    attn_kernel<<<ga, 128>>>(p_q, p_k, p_v, p_x);

    // proj + bias + fused LayerNorm -> g_xp, g_ln
    dim3 gp(1, NTOK / TM);
    gemm_wide<6, CH><<<gp, 512, SMEM_SZ>>>(p_x, p_wp, proj_b, p_xp, p_ln, ln_w, ln_b);

    // fc1 + bias + GELU -> g_h (tf32)
    dim3 g1(HID / TN, NTOK / TM);
    gemm_wide<1, CH><<<g1, 512, SMEM_SZ>>>(p_ln, p_w1, fc1_b, p_h, nullptr, nullptr, nullptr);

    // fc2 + bias + residual, transposed store -> d_out [B][C][H][W]
    dim3 g2(1, NTOK / TM);
    gemm_wide<2, HID><<<g2, 512, SMEM_SZ>>>(p_h, p_w2, fc2_b, out, p_xp, nullptr, nullptr);
}

// round 6
// speedup vs baseline: 1.5541x; 1.5541x over previous
#include <cuda_runtime.h>
#include <cuda_fp16.h>
#include <math.h>
#include <stdint.h>

// ---------------- problem constants ----------------
#define BATCH   8
#define CH      256
#define HH      64
#define WW      64
#define HWSZ    (HH*WW)          // 4096
#define NTOK    (BATCH*HWSZ)     // 32768
#define HID     1024
#define NHEAD   8
#define HDIM    32
#define CP2     (CH/2)           // 128 channel pairs

// ---------------- scratch ----------------
__device__ __half  g_ts[NTOK*CH];        // sub transposed [tok][c]
__device__ __half  g_to[NTOK*CH];        // ori transposed [tok][c]
__device__ __half2 g_q [BATCH*CP2*HWSZ]; // channel-pair-major
__device__ __half2 g_k [BATCH*CP2*HWSZ];
__device__ __half2 g_v [BATCH*CP2*HWSZ];
__device__ __half2 g_x [NTOK*CP2];       // attention out, [tok][c] as pairs
__device__ float   g_xp[NTOK*CH];        // proj out fp32 (residual/LN in)
__device__ __half  g_ln[NTOK*CH];        // layernorm out
__device__ __half  g_h [NTOK*HID];       // mlp hidden
__device__ __half  g_wq[CH*CH];          // fp16 weights
__device__ __half  g_wk[CH*CH];
__device__ __half  g_wv[CH*CH];
__device__ __half  g_wp[CH*CH];
__device__ __half  g_w1[HID*CH];
__device__ __half  g_w2[CH*HID];

// ---------------- helpers ----------------
__device__ __forceinline__ uint32_t smem_u32(const void* p) {
    uint32_t a;
    asm("{ .reg .u64 t; cvta.to.shared.u64 t, %1; cvt.u32.u64 %0, t; }"
        : "=r"(a) : "l"(p));
    return a;
}
__device__ __forceinline__ void cp16(uint32_t s, const void* g) {
    asm volatile("cp.async.cg.shared.global [%0], [%1], 16;" :: "r"(s), "l"(g));
}
#define CP_COMMIT() asm volatile("cp.async.commit_group;" ::: "memory")
#define CP_WAIT1()  asm volatile("cp.async.wait_group 1;" ::: "memory")

__device__ __forceinline__ void ldsm_x4(uint32_t r[4], uint32_t addr) {
    asm volatile("ldmatrix.sync.aligned.m8n8.x4.shared.b16 {%0,%1,%2,%3}, [%4];"
        : "=r"(r[0]), "=r"(r[1]), "=r"(r[2]), "=r"(r[3]) : "r"(addr));
}
__device__ __forceinline__ void mma_f16(float c[4], const uint32_t a[4],
                                        uint32_t b0, uint32_t b1) {
    asm volatile(
        "mma.sync.aligned.m16n8k16.row.col.f32.f16.f16.f32 "
        "{%0,%1,%2,%3}, {%4,%5,%6,%7}, {%8,%9}, {%0,%1,%2,%3};\n"
        : "+f"(c[0]), "+f"(c[1]), "+f"(c[2]), "+f"(c[3])
        : "r"(a[0]), "r"(a[1]), "r"(a[2]), "r"(a[3]), "r"(b0), "r"(b1));
}

// =====================================================================
// fp16 NT GEMM: C[m,n] = sum_k A[m,k] * W[n,k] + epilogue
// CTA 128x128, 256 threads (8 warps, warp = 32x64), K-chunk 64 halves
// (128B/row), 2-stage cp.async, ldmatrix, swizzled smem rows.
// MODE 4: qkv  -> no bias, half2 channel-pair transposed store
// MODE 0: proj -> +bias, store fp32 [m][CH] (g_xp)
// MODE 1: fc1  -> +bias, exact GELU, half store [m][HID]
// MODE 2: fc2  -> +bias +resid fp32[m][n], transposed fp32 store [B][C][H][W]
// =====================================================================
#define STAGE_B 32768   // 16KB A + 16KB B
#define SMEM_SZ (2*STAGE_B)

template<int MODE, int KDIM>
__global__ __launch_bounds__(256, 2)
void gemm_h(const __half* __restrict__ A, const __half* __restrict__ Wt,
            const float* __restrict__ bias, void* __restrict__ out1,
            const float* __restrict__ resid)
{
    extern __shared__ __align__(128) char smem[];
    const uint32_t sb = smem_u32(smem);

    const int tid  = threadIdx.x;
    const int lane = tid & 31;
    const int wid  = tid >> 5;
    const int wm   = wid & 3;      // m: 32-row block
    const int wn   = wid >> 2;     // n: 64-col block
    const int lq   = lane >> 2;
    const int lr   = lane & 3;

    const int nT = blockIdx.x * 128;
    const int mT = blockIdx.y * 128;
    const int NCH = KDIM / 64;

    // A fragment rows: lane&15 within m16 tile, (lane>>4) selects k8 half
    const int arow  = wm * 32 + (lane & 15);
    const int aqsel = lane >> 4;
    const uint32_t abase0 = (uint32_t)arow * 128;
    const uint32_t abase1 = (uint32_t)(arow + 16) * 128;
    const int axor = arow & 7;
    // B fragment rows: n16 group, lane&15 within, (lane>>4) selects k8 half
    const int brow  = wn * 64 + (lane & 15);
    const int bqsel = lane >> 4;

    float acc[2][8][4];
    #pragma unroll
    for (int i = 0; i < 2; i++)
        #pragma unroll
        for (int j = 0; j < 8; j++)
            #pragma unroll
            for (int u = 0; u < 4; u++) acc[i][j][u] = 0.f;

    auto load_stage = [&](int s, int kt) {
        const uint32_t ab = sb + s * STAGE_B;
        const uint32_t bbm = ab + 16384;
        #pragma unroll
        for (int j = 0; j < 4; j++) {
            int c = tid + j * 256;          // 0..1023
            int row = c >> 3, q = c & 7;    // 128 rows x 8 q16
            uint32_t off = (uint32_t)row * 128 + (uint32_t)((q ^ (row & 7)) * 16);
            cp16(ab  + off, A  + (size_t)(mT + row) * KDIM + kt + q * 8);
            cp16(bbm + off, Wt + (size_t)(nT + row) * KDIM + kt + q * 8);
        }
    };

    load_stage(0, 0);  CP_COMMIT();
    if (NCH > 1) load_stage(1, 64);
    CP_COMMIT();

    for (int it = 0; it < NCH; it++) {
        const int s = it & 1;
        CP_WAIT1();
        __syncthreads();

        const uint32_t ab = sb + s * STAGE_B;
        const uint32_t bbm = ab + 16384;

        #pragma unroll
        for (int ks = 0; ks < 4; ks++) {          // 4 x k16
            const int q0 = ks * 2;
            uint32_t af[2][4];
            {
                const int qa = q0 + aqsel;
                ldsm_x4(af[0], ab + abase0 + (uint32_t)((qa ^ axor) * 16));
                ldsm_x4(af[1], ab + abase1 + (uint32_t)((qa ^ axor) * 16));
            }
            #pragma unroll
            for (int nt2 = 0; nt2 < 4; nt2++) {   // 4 x n16
                const int row = brow + nt2 * 16;
                const int qb = q0 + bqsel;
                uint32_t bf[4];
                ldsm_x4(bf, bbm + (uint32_t)row * 128 + (uint32_t)((qb ^ (row & 7)) * 16));
                // bf: [0]=(n0-7,k0-7) [1]=(n8-15,k0-7) [2]=(n0-7,k8-15) [3]=(n8-15,k8-15)
                mma_f16(acc[0][nt2*2  ], af[0], bf[0], bf[2]);
                mma_f16(acc[0][nt2*2+1], af[0], bf[1], bf[3]);
                mma_f16(acc[1][nt2*2  ], af[1], bf[0], bf[2]);
                mma_f16(acc[1][nt2*2+1], af[1], bf[1], bf[3]);
            }
        }
        __syncthreads();
        if (it + 2 < NCH) load_stage(s, (it + 2) * 64);
        CP_COMMIT();
    }

    // ---------------- epilogue ----------------
    #pragma unroll
    for (int mt = 0; mt < 2; mt++) {
        #pragma unroll
        for (int idx = 0; idx < 8; idx++) {
            const int nt2 = idx >> 1, tt = idx & 1;
            const int m0 = mT + wm * 32 + mt * 16 + lq;
            const int n0 = nT + wn * 64 + nt2 * 16 + tt * 8 + (lr << 1);
            const float* cc = acc[mt][idx];

            if (MODE == 4) {
                // qkv: half2 channel-pair transposed store
                const int bi = m0 >> 12;
                const int hw = m0 & 4095;
                __half2* p = (__half2*)out1 + (size_t)bi * CP2 * HWSZ
                           + (size_t)(n0 >> 1) * HWSZ;
                p[hw    ] = __floats2half2_rn(cc[0], cc[1]);
                p[hw + 8] = __floats2half2_rn(cc[2], cc[3]);
            } else if (MODE == 0) {
                float* o = (float*)out1;
                float2 bv = *(const float2*)&bias[n0];
                *(float2*)&o[(size_t)m0 * CH + n0] =
                    make_float2(cc[0] + bv.x, cc[1] + bv.y);
                *(float2*)&o[(size_t)(m0 + 8) * CH + n0] =
                    make_float2(cc[2] + bv.x, cc[3] + bv.y);
            } else if (MODE == 1) {
                __half* o = (__half*)out1;
                float2 bv = *(const float2*)&bias[n0];
                float v[4] = {cc[0] + bv.x, cc[1] + bv.y, cc[2] + bv.x, cc[3] + bv.y};
                #pragma unroll
                for (int u = 0; u < 4; u++)
                    v[u] = 0.5f * v[u] * (1.f + erff(v[u] * 0.70710678118654752f));
                *(__half2*)&o[(size_t)m0 * HID + n0]       = __floats2half2_rn(v[0], v[1]);
                *(__half2*)&o[(size_t)(m0 + 8) * HID + n0] = __floats2half2_rn(v[2], v[3]);
            } else {
                float* o = (float*)out1;
                float2 bv = *(const float2*)&bias[n0];
                float2 r0 = *(const float2*)&resid[(size_t)m0 * CH + n0];
                float2 r1 = *(const float2*)&resid[(size_t)(m0 + 8) * CH + n0];
                const int bi = m0 >> 12;
                const int hw = m0 & 4095;
                float* p = o + (size_t)bi * CH * HWSZ;
                p[(size_t)(n0    ) * HWSZ + hw    ] = cc[0] + bv.x + r0.x;
                p[(size_t)(n0 + 1) * HWSZ + hw    ] = cc[1] + bv.y + r0.y;
                p[(size_t)(n0    ) * HWSZ + hw + 8] = cc[2] + bv.x + r1.x;
                p[(size_t)(n0 + 1) * HWSZ + hw + 8] = cc[3] + bv.y + r1.y;
            }
        }
    }
}

// =====================================================================
// Tiled transpose + fp16 cvt: [b][256][4096] fp32 -> [b*4096][256] fp16
// =====================================================================
__global__ void transpose_h(const float* __restrict__ in, __half* __restrict__ out)
{
    __shared__ float t[32][33];
    const int b  = blockIdx.z;
    const int p0 = blockIdx.x * 32;
    const int c0 = blockIdx.y * 32;
    const int tx = threadIdx.x, ty = threadIdx.y;   // 32 x 8
    const float* ib = in + (size_t)b * CH * HWSZ;
    __half* ob = out + (size_t)b * HWSZ * CH;
    #pragma unroll
    for (int i = 0; i < 4; i++)
        t[ty + 8*i][tx] = ib[(size_t)(c0 + ty + 8*i) * HWSZ + p0 + tx];
    __syncthreads();
    #pragma unroll
    for (int i = 0; i < 4; i++)
        ob[(size_t)(p0 + ty + 8*i) * CH + c0 + tx] = __float2half_rn(t[tx][ty + 8*i]);
}

// =====================================================================
// Dilated 3x3 local attention, fp16 channel-pair buffers, fp32 math.
// 1 thread = (pixel, head).
// =====================================================================
__global__ void attn_kernel(const __half2* __restrict__ q,
                            const __half2* __restrict__ k,
                            const __half2* __restrict__ v,
                            __half2* __restrict__ xo)
{
    const int b    = blockIdx.z;
    const int head = blockIdx.y;
    const int n    = blockIdx.x * 128 + threadIdx.x;
    const int py   = n >> 6;
    const int px   = n & 63;
    const int dil  = (head >> 1) + 1;

    const size_t base = ((size_t)b * CP2 + head * (HDIM/2)) * HWSZ;
    const __half2* qb = q + base + n;
    const __half2* kb = k + base;
    const __half2* vb = v + base;

    float2 qr[16];
    #pragma unroll
    for (int cp = 0; cp < 16; cp++) qr[cp] = __half22float2(qb[(size_t)cp * HWSZ]);

    int nn[9];
    #pragma unroll
    for (int t = 0; t < 9; t++) {
        int yy = py + (t / 3 - 1) * dil;
        int xx = px + (t % 3 - 1) * dil;
        nn[t] = (yy >= 0 && yy < HH && xx >= 0 && xx < WW) ? (yy * WW + xx) : -1;
    }

    float logit[9];
    #pragma unroll
    for (int t = 0; t < 9; t++) {
        float acc = 0.f;
        if (nn[t] >= 0) {
            #pragma unroll
            for (int cp = 0; cp < 16; cp++) {
                float2 kv = __half22float2(kb[(size_t)cp * HWSZ + nn[t]]);
                acc += qr[cp].x * kv.x + qr[cp].y * kv.y;
            }
        }
        logit[t] = acc * 0.17677669529663687f;
    }

    float mx = logit[0];
    #pragma unroll
    for (int t = 1; t < 9; t++) mx = fmaxf(mx, logit[t]);
    float s = 0.f;
    #pragma unroll
    for (int t = 0; t < 9; t++) { logit[t] = __expf(logit[t] - mx); s += logit[t]; }
    const float inv = 1.f / s;
    #pragma unroll
    for (int t = 0; t < 9; t++) logit[t] *= inv;

    __half2* xrow = xo + (size_t)(b * HWSZ + n) * CP2 + head * (HDIM/2);
    #pragma unroll
    for (int cp = 0; cp < 16; cp++) {
        float ox = 0.f, oy = 0.f;
        #pragma unroll
        for (int t = 0; t < 9; t++)
            if (nn[t] >= 0) {
                float2 vv = __half22float2(vb[(size_t)cp * HWSZ + nn[t]]);
                ox += logit[t] * vv.x;
                oy += logit[t] * vv.y;
            }
        xrow[cp] = __floats2half2_rn(ox, oy);
    }
}

// =====================================================================
// LayerNorm over 256 channels: fp32 in (g_xp), fp16 out (g_ln).
// =====================================================================
__global__ void ln_kernel(const float* __restrict__ xp,
                          const float* __restrict__ w,
                          const float* __restrict__ bb,
                          __half2* __restrict__ out)
{
    const int warp = threadIdx.x >> 5;
    const int lane = threadIdx.x & 31;
    const int tok  = blockIdx.x * 8 + warp;
    const float* row = xp + (size_t)tok * CH;

    float4 v0 = *(const float4*)&row[lane * 8];
    float4 v1 = *(const float4*)&row[lane * 8 + 4];
    float va[8] = {v0.x, v0.y, v0.z, v0.w, v1.x, v1.y, v1.z, v1.w};

    float s = 0.f, sq = 0.f;
    #pragma unroll
    for (int u = 0; u < 8; u++) { s += va[u]; sq += va[u] * va[u]; }
    #pragma unroll
    for (int o = 16; o; o >>= 1) {
        s  += __shfl_xor_sync(0xffffffffu, s,  o);
        sq += __shfl_xor_sync(0xffffffffu, sq, o);
    }
    const float mean = s * (1.f / 256.f);
    const float var  = sq * (1.f / 256.f) - mean * mean;
    const float inv  = rsqrtf(var + 1e-5f);

    __half2* orow = out + (size_t)tok * CP2 + lane * 4;
    #pragma unroll
    for (int j = 0; j < 4; j++) {
        int ch = lane * 8 + j * 2;
        float a0 = (va[j*2]   - mean) * inv * w[ch]     + bb[ch];
        float a1 = (va[j*2+1] - mean) * inv * w[ch + 1] + bb[ch + 1];
        orow[j] = __floats2half2_rn(a0, a1);
    }
}

// ---------------- weight fp32 -> fp16 ----------------
__global__ void cvt_h(const float* __restrict__ a, __half* __restrict__ b, int n)
{
    int i = blockIdx.x * 256 + threadIdx.x;
    if (i < n) b[i] = __float2half_rn(a[i]);
}

// =====================================================================
extern "C" void kernel_launch(void* const* d_in, const int* in_sizes, int n_in,
                              void* d_out, int out_size)
{
    const float* sub    = (const float*)d_in[0];
    const float* ori    = (const float*)d_in[1];
    const float* wq     = (const float*)d_in[2];
    const float* wk     = (const float*)d_in[3];
    const float* wv     = (const float*)d_in[4];
    const float* proj_w = (const float*)d_in[5];
    const float* proj_b = (const float*)d_in[6];
    const float* ln_w   = (const float*)d_in[7];
    const float* ln_b   = (const float*)d_in[8];
    const float* fc1_w  = (const float*)d_in[9];
    const float* fc1_b  = (const float*)d_in[10];
    const float* fc2_w  = (const float*)d_in[11];
    const float* fc2_b  = (const float*)d_in[12];
    float* out = (float*)d_out;

    __half *p_ts, *p_to, *p_ln, *p_h, *p_wq, *p_wk, *p_wv, *p_wp, *p_w1, *p_w2;
    __half2 *p_q, *p_k, *p_v, *p_x;
    float *p_xp;
    cudaGetSymbolAddress((void**)&p_ts, g_ts);
    cudaGetSymbolAddress((void**)&p_to, g_to);
    cudaGetSymbolAddress((void**)&p_q,  g_q);
    cudaGetSymbolAddress((void**)&p_k,  g_k);
    cudaGetSymbolAddress((void**)&p_v,  g_v);
    cudaGetSymbolAddress((void**)&p_x,  g_x);
    cudaGetSymbolAddress((void**)&p_xp, g_xp);
    cudaGetSymbolAddress((void**)&p_ln, g_ln);
    cudaGetSymbolAddress((void**)&p_h,  g_h);
    cudaGetSymbolAddress((void**)&p_wq, g_wq);
    cudaGetSymbolAddress((void**)&p_wk, g_wk);
    cudaGetSymbolAddress((void**)&p_wv, g_wv);
    cudaGetSymbolAddress((void**)&p_wp, g_wp);
    cudaGetSymbolAddress((void**)&p_w1, g_w1);
    cudaGetSymbolAddress((void**)&p_w2, g_w2);

    cudaFuncSetAttribute(gemm_h<4, CH >, cudaFuncAttributeMaxDynamicSharedMemorySize, SMEM_SZ);
    cudaFuncSetAttribute(gemm_h<0, CH >, cudaFuncAttributeMaxDynamicSharedMemorySize, SMEM_SZ);
    cudaFuncSetAttribute(gemm_h<1, CH >, cudaFuncAttributeMaxDynamicSharedMemorySize, SMEM_SZ);
    cudaFuncSetAttribute(gemm_h<2, HID>, cudaFuncAttributeMaxDynamicSharedMemorySize, SMEM_SZ);

    // weight conversion
    cvt_h<<<(CH*CH  + 255) / 256, 256>>>(wq,     p_wq, CH*CH);
    cvt_h<<<(CH*CH  + 255) / 256, 256>>>(wk,     p_wk, CH*CH);
    cvt_h<<<(CH*CH  + 255) / 256, 256>>>(wv,     p_wv, CH*CH);
    cvt_h<<<(CH*CH  + 255) / 256, 256>>>(proj_w, p_wp, CH*CH);
    cvt_h<<<(HID*CH + 255) / 256, 256>>>(fc1_w,  p_w1, HID*CH);
    cvt_h<<<(CH*HID + 255) / 256, 256>>>(fc2_w,  p_w2, CH*HID);

    // transpose inputs to [tok][c] fp16
    dim3 gt(HWSZ / 32, CH / 32, BATCH);
    dim3 bt(32, 8);
    transpose_h<<<gt, bt>>>(sub, p_ts);
    transpose_h<<<gt, bt>>>(ori, p_to);

    // qkv (NT, half2 channel-pair transposed store)
    dim3 gq(CH / 128, NTOK / 128);       // (2, 256)
    gemm_h<4, CH><<<gq, 256, SMEM_SZ>>>(p_ts, p_wq, nullptr, p_q, nullptr);
    gemm_h<4, CH><<<gq, 256, SMEM_SZ>>>(p_to, p_wk, nullptr, p_k, nullptr);
    gemm_h<4, CH><<<gq, 256, SMEM_SZ>>>(p_to, p_wv, nullptr, p_v, nullptr);

    // attention -> g_x [tok][c] fp16
    dim3 ga(HWSZ / 128, NHEAD, BATCH);
    attn_kernel<<<ga, 128>>>(p_q, p_k, p_v, p_x);

    // proj + bias -> g_xp fp32
    dim3 gp(CH / 128, NTOK / 128);
    gemm_h<0, CH><<<gp, 256, SMEM_SZ>>>((const __half*)p_x, p_wp, proj_b, p_xp, nullptr);

    // layernorm -> g_ln fp16
    ln_kernel<<<NTOK / 8, 256>>>(p_xp, ln_w, ln_b, (__half2*)p_ln);

    // fc1 + bias + GELU -> g_h fp16
    dim3 g1(HID / 128, NTOK / 128);      // (8, 256)
    gemm_h<1, CH><<<g1, 256, SMEM_SZ>>>(p_ln, p_w1, fc1_b, p_h, nullptr);

    // fc2 + bias + residual, transposed fp32 store -> d_out [B][C][H][W]
    dim3 g2(CH / 128, NTOK / 128);
    gemm_h<2, HID><<<g2, 256, SMEM_SZ>>>(p_h, p_w2, fc2_b, out, p_xp);
}

// round 7
// speedup vs baseline: 1.5949x; 1.0262x over previous
#include <cuda_runtime.h>
#include <cuda_fp16.h>
#include <math.h>
#include <stdint.h>

// ---------------- problem constants ----------------
#define BATCH   8
#define CH      256
#define HH      64
#define WW      64
#define HWSZ    (HH*WW)          // 4096
#define NTOK    (BATCH*HWSZ)     // 32768
#define HID     1024
#define NHEAD   8
#define HDIM    32
#define CP2     (CH/2)           // 128 channel pairs

// ---------------- scratch ----------------
__device__ __half  g_ts[NTOK*CH];        // sub transposed [tok][c]
__device__ __half  g_to[NTOK*CH];        // ori transposed [tok][c]
__device__ __half2 g_q [BATCH*CP2*HWSZ]; // channel-pair-major
__device__ __half2 g_k [BATCH*CP2*HWSZ];
__device__ __half2 g_v [BATCH*CP2*HWSZ];
__device__ __half2 g_x [NTOK*CP2];       // attention out, [tok][c] pairs
__device__ float   g_xp[NTOK*CH];        // proj out fp32 (residual/LN in)
__device__ __half  g_ln[NTOK*CH];        // layernorm out
__device__ __half  g_h [NTOK*HID];       // mlp hidden
__device__ __half  g_wq [CH*CH];         // fp16 weights
__device__ __half  g_wkv[2*CH*CH];       // wk rows 0..255 | wv rows 256..511
__device__ __half  g_wp [CH*CH];
__device__ __half  g_w1 [HID*CH];
__device__ __half  g_w2 [CH*HID];

// ---------------- helpers ----------------
__device__ __forceinline__ uint32_t smem_u32(const void* p) {
    uint32_t a;
    asm("{ .reg .u64 t; cvta.to.shared.u64 t, %1; cvt.u32.u64 %0, t; }"
        : "=r"(a) : "l"(p));
    return a;
}
__device__ __forceinline__ void cp16(uint32_t s, const void* g) {
    asm volatile("cp.async.cg.shared.global [%0], [%1], 16;" :: "r"(s), "l"(g));
}
#define CP_COMMIT() asm volatile("cp.async.commit_group;" ::: "memory")
#define CP_WAIT1()  asm volatile("cp.async.wait_group 1;" ::: "memory")

__device__ __forceinline__ void ldsm_x4(uint32_t r[4], uint32_t addr) {
    asm volatile("ldmatrix.sync.aligned.m8n8.x4.shared.b16 {%0,%1,%2,%3}, [%4];"
        : "=r"(r[0]), "=r"(r[1]), "=r"(r[2]), "=r"(r[3]) : "r"(addr));
}
__device__ __forceinline__ void mma_f16(float c[4], const uint32_t a[4],
                                        uint32_t b0, uint32_t b1) {
    asm volatile(
        "mma.sync.aligned.m16n8k16.row.col.f32.f16.f16.f32 "
        "{%0,%1,%2,%3}, {%4,%5,%6,%7}, {%8,%9}, {%0,%1,%2,%3};\n"
        : "+f"(c[0]), "+f"(c[1]), "+f"(c[2]), "+f"(c[3])
        : "r"(a[0]), "r"(a[1]), "r"(a[2]), "r"(a[3]), "r"(b0), "r"(b1));
}

// =====================================================================
// fp16 NT GEMM: C[m,n] = sum_k A[m,k] * W[n,k] + epilogue
// CTA 128x128, 256 threads (8 warps, warp = 32x64), K-chunk 64,
// 2-stage cp.async, ldmatrix, swizzled 128B smem rows.
// MODE 4: qkv single -> half2 channel-pair transposed store (out1)
// MODE 5: kv stacked -> n<256: out1 (k), n>=256: aux (v)
// MODE 0: proj -> +bias, fp32 store [m][CH]
// MODE 1: fc1  -> +bias, exact GELU, half store [m][HID]
// MODE 2: fc2  -> +bias +resid fp32 (aux), transposed fp32 store [B][C][H][W]
// =====================================================================
#define STAGE_B 32768   // 16KB A + 16KB B
#define SMEM_SZ (2*STAGE_B)

template<int MODE, int KDIM>
__global__ __launch_bounds__(256, 2)
void gemm_h(const __half* __restrict__ A, const __half* __restrict__ Wt,
            const float* __restrict__ bias, void* __restrict__ out1,
            void* __restrict__ aux)
{
    extern __shared__ __align__(128) char smem[];
    const uint32_t sb = smem_u32(smem);

    const int tid  = threadIdx.x;
    const int lane = tid & 31;
    const int wid  = tid >> 5;
    const int wm   = wid & 3;
    const int wn   = wid >> 2;
    const int lq   = lane >> 2;
    const int lr   = lane & 3;

    const int nT = blockIdx.x * 128;
    const int mT = blockIdx.y * 128;
    const int NCH = KDIM / 64;

    const int arow  = wm * 32 + (lane & 15);
    const int aqsel = lane >> 4;
    const uint32_t abase0 = (uint32_t)arow * 128;
    const uint32_t abase1 = (uint32_t)(arow + 16) * 128;
    const int axor = arow & 7;
    const int brow  = wn * 64 + (lane & 15);
    const int bqsel = lane >> 4;

    float acc[2][8][4];
    #pragma unroll
    for (int i = 0; i < 2; i++)
        #pragma unroll
        for (int j = 0; j < 8; j++)
            #pragma unroll
            for (int u = 0; u < 4; u++) acc[i][j][u] = 0.f;

    auto load_stage = [&](int s, int kt) {
        const uint32_t ab = sb + s * STAGE_B;
        const uint32_t bbm = ab + 16384;
        #pragma unroll
        for (int j = 0; j < 4; j++) {
            int c = tid + j * 256;
            int row = c >> 3, q = c & 7;
            uint32_t off = (uint32_t)row * 128 + (uint32_t)((q ^ (row & 7)) * 16);
            cp16(ab  + off, A  + (size_t)(mT + row) * KDIM + kt + q * 8);
            cp16(bbm + off, Wt + (size_t)(nT + row) * KDIM + kt + q * 8);
        }
    };

    load_stage(0, 0);  CP_COMMIT();
    if (NCH > 1) load_stage(1, 64);
    CP_COMMIT();

    for (int it = 0; it < NCH; it++) {
        const int s = it & 1;
        CP_WAIT1();
        __syncthreads();

        const uint32_t ab = sb + s * STAGE_B;
        const uint32_t bbm = ab + 16384;

        #pragma unroll
        for (int ks = 0; ks < 4; ks++) {
            const int q0 = ks * 2;
            uint32_t af[2][4];
            {
                const int qa = q0 + aqsel;
                ldsm_x4(af[0], ab + abase0 + (uint32_t)((qa ^ axor) * 16));
                ldsm_x4(af[1], ab + abase1 + (uint32_t)((qa ^ axor) * 16));
            }
            #pragma unroll
            for (int nt2 = 0; nt2 < 4; nt2++) {
                const int row = brow + nt2 * 16;
                const int qb = q0 + bqsel;
                uint32_t bf[4];
                ldsm_x4(bf, bbm + (uint32_t)row * 128 + (uint32_t)((qb ^ (row & 7)) * 16));
                mma_f16(acc[0][nt2*2  ], af[0], bf[0], bf[2]);
                mma_f16(acc[0][nt2*2+1], af[0], bf[1], bf[3]);
                mma_f16(acc[1][nt2*2  ], af[1], bf[0], bf[2]);
                mma_f16(acc[1][nt2*2+1], af[1], bf[1], bf[3]);
            }
        }
        __syncthreads();
        if (it + 2 < NCH) load_stage(s, (it + 2) * 64);
        CP_COMMIT();
    }

    // ---------------- epilogue ----------------
    #pragma unroll
    for (int mt = 0; mt < 2; mt++) {
        #pragma unroll
        for (int idx = 0; idx < 8; idx++) {
            const int nt2 = idx >> 1, tt = idx & 1;
            const int m0 = mT + wm * 32 + mt * 16 + lq;
            const int n0 = nT + wn * 64 + nt2 * 16 + tt * 8 + (lr << 1);
            const float* cc = acc[mt][idx];

            if (MODE == 4 || MODE == 5) {
                const int bi = m0 >> 12;
                const int hw = m0 & 4095;
                __half2* dst;
                int ch;
                if (MODE == 5) {
                    dst = (n0 < CH) ? (__half2*)out1 : (__half2*)aux;
                    ch = n0 & (CH - 1);
                } else { dst = (__half2*)out1; ch = n0; }
                __half2* p = dst + (size_t)bi * CP2 * HWSZ + (size_t)(ch >> 1) * HWSZ;
                p[hw    ] = __floats2half2_rn(cc[0], cc[1]);
                p[hw + 8] = __floats2half2_rn(cc[2], cc[3]);
            } else if (MODE == 0) {
                float* o = (float*)out1;
                float2 bv = *(const float2*)&bias[n0];
                *(float2*)&o[(size_t)m0 * CH + n0] =
                    make_float2(cc[0] + bv.x, cc[1] + bv.y);
                *(float2*)&o[(size_t)(m0 + 8) * CH + n0] =
                    make_float2(cc[2] + bv.x, cc[3] + bv.y);
            } else if (MODE == 1) {
                __half* o = (__half*)out1;
                float2 bv = *(const float2*)&bias[n0];
                float v[4] = {cc[0] + bv.x, cc[1] + bv.y, cc[2] + bv.x, cc[3] + bv.y};
                #pragma unroll
                for (int u = 0; u < 4; u++)
                    v[u] = 0.5f * v[u] * (1.f + erff(v[u] * 0.70710678118654752f));
                *(__half2*)&o[(size_t)m0 * HID + n0]       = __floats2half2_rn(v[0], v[1]);
                *(__half2*)&o[(size_t)(m0 + 8) * HID + n0] = __floats2half2_rn(v[2], v[3]);
            } else {
                float* o = (float*)out1;
                const float* resid = (const float*)aux;
                float2 bv = *(const float2*)&bias[n0];
                float2 r0 = *(const float2*)&resid[(size_t)m0 * CH + n0];
                float2 r1 = *(const float2*)&resid[(size_t)(m0 + 8) * CH + n0];
                const int bi = m0 >> 12;
                const int hw = m0 & 4095;
                float* p = o + (size_t)bi * CH * HWSZ;
                p[(size_t)(n0    ) * HWSZ + hw    ] = cc[0] + bv.x + r0.x;
                p[(size_t)(n0 + 1) * HWSZ + hw    ] = cc[1] + bv.y + r0.y;
                p[(size_t)(n0    ) * HWSZ + hw + 8] = cc[2] + bv.x + r1.x;
                p[(size_t)(n0 + 1) * HWSZ + hw + 8] = cc[3] + bv.y + r1.y;
            }
        }
    }
}

// =====================================================================
// Tiled transpose + fp16 cvt: [b][256][4096] fp32 -> [b*4096][256] fp16
// =====================================================================
__global__ void transpose_h(const float* __restrict__ in, __half* __restrict__ out)
{
    __shared__ float t[32][33];
    const int b  = blockIdx.z;
    const int p0 = blockIdx.x * 32;
    const int c0 = blockIdx.y * 32;
    const int tx = threadIdx.x, ty = threadIdx.y;   // 32 x 8
    const float* ib = in + (size_t)b * CH * HWSZ;
    __half* ob = out + (size_t)b * HWSZ * CH;
    #pragma unroll
    for (int i = 0; i < 4; i++)
        t[ty + 8*i][tx] = ib[(size_t)(c0 + ty + 8*i) * HWSZ + p0 + tx];
    __syncthreads();
    #pragma unroll
    for (int i = 0; i < 4; i++)
        ob[(size_t)(p0 + ty + 8*i) * CH + c0 + tx] = __float2half_rn(t[tx][ty + 8*i]);
}

// =====================================================================
// Dilated 3x3 local attention, branchless gathers (clamped idx + mask).
// fp16 channel-pair buffers, fp32 math. 1 thread = (pixel, head).
// =====================================================================
__global__ __launch_bounds__(128)
void attn_kernel(const __half2* __restrict__ q,
                 const __half2* __restrict__ k,
                 const __half2* __restrict__ v,
                 __half2* __restrict__ xo)
{
    const int b    = blockIdx.z;
    const int head = blockIdx.y;
    const int n    = blockIdx.x * 128 + threadIdx.x;
    const int py   = n >> 6;
    const int px   = n & 63;
    const int dil  = (head >> 1) + 1;

    const size_t base = ((size_t)b * CP2 + head * (HDIM/2)) * HWSZ;
    const __half2* qb = q + base + n;
    const __half2* kb = k + base;
    const __half2* vb = v + base;

    float2 qr[16];
    #pragma unroll
    for (int cp = 0; cp < 16; cp++) qr[cp] = __half22float2(qb[(size_t)cp * HWSZ]);

    int nn[9];
    float msk[9];
    #pragma unroll
    for (int t = 0; t < 9; t++) {
        int yy = py + (t / 3 - 1) * dil;
        int xx = px + (t % 3 - 1) * dil;
        const bool in = (yy >= 0 && yy < HH && xx >= 0 && xx < WW);
        nn[t] = in ? (yy * WW + xx) : n;     // clamp to self (safe address)
        msk[t] = in ? 1.f : 0.f;
    }

    float logit[9];
    #pragma unroll
    for (int t = 0; t < 9; t++) {
        float acc = 0.f;
        #pragma unroll
        for (int cp = 0; cp < 16; cp++) {
            float2 kv = __half22float2(kb[(size_t)cp * HWSZ + nn[t]]);
            acc += qr[cp].x * kv.x + qr[cp].y * kv.y;
        }
        logit[t] = acc * msk[t] * 0.17677669529663687f;   // OOB -> exactly 0
    }

    float mx = logit[0];
    #pragma unroll
    for (int t = 1; t < 9; t++) mx = fmaxf(mx, logit[t]);
    float s = 0.f;
    #pragma unroll
    for (int t = 0; t < 9; t++) { logit[t] = __expf(logit[t] - mx); s += logit[t]; }
    const float inv = 1.f / s;
    #pragma unroll
    for (int t = 0; t < 9; t++) logit[t] *= inv * msk[t];  // OOB v contributes 0

    __half2* xrow = xo + (size_t)(b * HWSZ + n) * CP2 + head * (HDIM/2);
    #pragma unroll
    for (int cp = 0; cp < 16; cp++) {
        float ox = 0.f, oy = 0.f;
        #pragma unroll
        for (int t = 0; t < 9; t++) {
            float2 vv = __half22float2(vb[(size_t)cp * HWSZ + nn[t]]);
            ox += logit[t] * vv.x;
            oy += logit[t] * vv.y;
        }
        xrow[cp] = __floats2half2_rn(ox, oy);
    }
}

// =====================================================================
// LayerNorm over 256 channels: fp32 in (g_xp), fp16 out (g_ln).
// =====================================================================
__global__ void ln_kernel(const float* __restrict__ xp,
                          const float* __restrict__ w,
                          const float* __restrict__ bb,
                          __half2* __restrict__ out)
{
    const int warp = threadIdx.x >> 5;
    const int lane = threadIdx.x & 31;
    const int tok  = blockIdx.x * 8 + warp;
    const float* row = xp + (size_t)tok * CH;

    float4 v0 = *(const float4*)&row[lane * 8];
    float4 v1 = *(const float4*)&row[lane * 8 + 4];
    float va[8] = {v0.x, v0.y, v0.z, v0.w, v1.x, v1.y, v1.z, v1.w};

    float s = 0.f, sq = 0.f;
    #pragma unroll
    for (int u = 0; u < 8; u++) { s += va[u]; sq += va[u] * va[u]; }
    #pragma unroll
    for (int o = 16; o; o >>= 1) {
        s  += __shfl_xor_sync(0xffffffffu, s,  o);
        sq += __shfl_xor_sync(0xffffffffu, sq, o);
    }
    const float mean = s * (1.f / 256.f);
    const float var  = sq * (1.f / 256.f) - mean * mean;
    const float inv  = rsqrtf(var + 1e-5f);

    __half2* orow = out + (size_t)tok * CP2 + lane * 4;
    #pragma unroll
    for (int j = 0; j < 4; j++) {
        int ch = lane * 8 + j * 2;
        float a0 = (va[j*2]   - mean) * inv * w[ch]     + bb[ch];
        float a1 = (va[j*2+1] - mean) * inv * w[ch + 1] + bb[ch + 1];
        orow[j] = __floats2half2_rn(a0, a1);
    }
}

// ---------------- weight fp32 -> fp16 ----------------
__global__ void cvt_h(const float* __restrict__ a, __half* __restrict__ b, int n)
{
    int i = blockIdx.x * 256 + threadIdx.x;
    if (i < n) b[i] = __float2half_rn(a[i]);
}

// =====================================================================
extern "C" void kernel_launch(void* const* d_in, const int* in_sizes, int n_in,
                              void* d_out, int out_size)
{
    const float* sub    = (const float*)d_in[0];
    const float* ori    = (const float*)d_in[1];
    const float* wq     = (const float*)d_in[2];
    const float* wk     = (const float*)d_in[3];
    const float* wv     = (const float*)d_in[4];
    const float* proj_w = (const float*)d_in[5];
    const float* proj_b = (const float*)d_in[6];
    const float* ln_w   = (const float*)d_in[7];
    const float* ln_b   = (const float*)d_in[8];
    const float* fc1_w  = (const float*)d_in[9];
    const float* fc1_b  = (const float*)d_in[10];
    const float* fc2_w  = (const float*)d_in[11];
    const float* fc2_b  = (const float*)d_in[12];
    float* out = (float*)d_out;

    __half *p_ts, *p_to, *p_ln, *p_h, *p_wq, *p_wkv, *p_wp, *p_w1, *p_w2;
    __half2 *p_q, *p_k, *p_v, *p_x;
    float *p_xp;
    cudaGetSymbolAddress((void**)&p_ts,  g_ts);
    cudaGetSymbolAddress((void**)&p_to,  g_to);
    cudaGetSymbolAddress((void**)&p_q,   g_q);
    cudaGetSymbolAddress((void**)&p_k,   g_k);
    cudaGetSymbolAddress((void**)&p_v,   g_v);
    cudaGetSymbolAddress((void**)&p_x,   g_x);
    cudaGetSymbolAddress((void**)&p_xp,  g_xp);
    cudaGetSymbolAddress((void**)&p_ln,  g_ln);
    cudaGetSymbolAddress((void**)&p_h,   g_h);
    cudaGetSymbolAddress((void**)&p_wq,  g_wq);
    cudaGetSymbolAddress((void**)&p_wkv, g_wkv);
    cudaGetSymbolAddress((void**)&p_wp,  g_wp);
    cudaGetSymbolAddress((void**)&p_w1,  g_w1);
    cudaGetSymbolAddress((void**)&p_w2,  g_w2);

    cudaFuncSetAttribute(gemm_h<4, CH >, cudaFuncAttributeMaxDynamicSharedMemorySize, SMEM_SZ);
    cudaFuncSetAttribute(gemm_h<5, CH >, cudaFuncAttributeMaxDynamicSharedMemorySize, SMEM_SZ);
    cudaFuncSetAttribute(gemm_h<0, CH >, cudaFuncAttributeMaxDynamicSharedMemorySize, SMEM_SZ);
    cudaFuncSetAttribute(gemm_h<1, CH >, cudaFuncAttributeMaxDynamicSharedMemorySize, SMEM_SZ);
    cudaFuncSetAttribute(gemm_h<2, HID>, cudaFuncAttributeMaxDynamicSharedMemorySize, SMEM_SZ);

    // ---- launches 0..4 (prologue), launch 5 = q GEMM (ncu -s 5 -c 1 slot) ----
    cvt_h<<<(CH*CH + 255) / 256, 256>>>(wq, p_wq, CH*CH);                 // 0
    cvt_h<<<(CH*CH + 255) / 256, 256>>>(wk, p_wkv,         CH*CH);        // 1
    cvt_h<<<(CH*CH + 255) / 256, 256>>>(wv, p_wkv + CH*CH, CH*CH);        // 2
    dim3 gt(HWSZ / 32, CH / 32, BATCH);
    dim3 bt(32, 8);
    transpose_h<<<gt, bt>>>(sub, p_ts);                                    // 3
    transpose_h<<<gt, bt>>>(ori, p_to);                                    // 4

    dim3 gq(CH / 128, NTOK / 128);       // (2, 256)
    gemm_h<4, CH><<<gq, 256, SMEM_SZ>>>(p_ts, p_wq, nullptr, p_q, nullptr);  // 5

    // stacked k|v: N=512, reads g_to once
    dim3 gkv(2 * CH / 128, NTOK / 128);  // (4, 256)
    gemm_h<5, CH><<<gkv, 256, SMEM_SZ>>>(p_to, p_wkv, nullptr, p_k, p_v);

    // remaining weight conversions (independent; placed after ncu slot)
    cvt_h<<<(CH*CH  + 255) / 256, 256>>>(proj_w, p_wp, CH*CH);
    cvt_h<<<(HID*CH + 255) / 256, 256>>>(fc1_w,  p_w1, HID*CH);
    cvt_h<<<(CH*HID + 255) / 256, 256>>>(fc2_w,  p_w2, CH*HID);

    // attention -> g_x [tok][c] fp16
    dim3 ga(HWSZ / 128, NHEAD, BATCH);
    attn_kernel<<<ga, 128>>>(p_q, p_k, p_v, p_x);

    // proj + bias -> g_xp fp32
    dim3 gp(CH / 128, NTOK / 128);
    gemm_h<0, CH><<<gp, 256, SMEM_SZ>>>((const __half*)p_x, p_wp, proj_b, p_xp, nullptr);

    // layernorm -> g_ln fp16
    ln_kernel<<<NTOK / 8, 256>>>(p_xp, ln_w, ln_b, (__half2*)p_ln);

    // fc1 + bias + GELU -> g_h fp16
    dim3 g1(HID / 128, NTOK / 128);
    gemm_h<1, CH><<<g1, 256, SMEM_SZ>>>(p_ln, p_w1, fc1_b, p_h, nullptr);

    // fc2 + bias + residual, transposed fp32 store -> d_out [B][C][H][W]
    dim3 g2(CH / 128, NTOK / 128);
    gemm_h<2, HID><<<g2, 256, SMEM_SZ>>>(p_h, p_w2, fc2_b, out, p_xp);
}

// round 8
// speedup vs baseline: 1.6097x; 1.0093x over previous
#include <cuda_runtime.h>
#include <cuda_fp16.h>
#include <math.h>
#include <stdint.h>

// ---------------- problem constants ----------------
#define BATCH   8
#define CH      256
#define HH      64
#define WW      64
#define HWSZ    (HH*WW)          // 4096
#define NTOK    (BATCH*HWSZ)     // 32768
#define HID     1024
#define NHEAD   8
#define HDIM    32
#define CP2     (CH/2)           // 128 channel pairs

// ---------------- scratch ----------------
__device__ __half  g_ts[NTOK*CH];        // sub transposed [tok][c]
__device__ __half  g_to[NTOK*CH];        // ori transposed [tok][c]
__device__ __half2 g_q [BATCH*CP2*HWSZ]; // channel-pair-major
__device__ __half2 g_k [BATCH*CP2*HWSZ];
__device__ __half2 g_v [BATCH*CP2*HWSZ];
__device__ __half2 g_x [NTOK*CP2];       // attention out, [tok][c] pairs
__device__ float   g_xp[NTOK*CH];        // proj out fp32 (residual/LN in)
__device__ __half  g_ln[NTOK*CH];        // layernorm out
__device__ __half  g_h [NTOK*HID];       // mlp hidden
__device__ __half  g_wq [CH*CH];         // fp16 weights
__device__ __half  g_wkv[2*CH*CH];       // wk rows 0..255 | wv rows 256..511
__device__ __half  g_wp [CH*CH];
__device__ __half  g_w1 [HID*CH];
__device__ __half  g_w2 [CH*HID];

// ---------------- helpers ----------------
__device__ __forceinline__ uint32_t smem_u32(const void* p) {
    uint32_t a;
    asm("{ .reg .u64 t; cvta.to.shared.u64 t, %1; cvt.u32.u64 %0, t; }"
        : "=r"(a) : "l"(p));
    return a;
}
__device__ __forceinline__ void cp16(uint32_t s, const void* g) {
    asm volatile("cp.async.cg.shared.global [%0], [%1], 16;" :: "r"(s), "l"(g));
}
#define CP_COMMIT() asm volatile("cp.async.commit_group;" ::: "memory")
#define CP_WAIT2()  asm volatile("cp.async.wait_group 2;" ::: "memory")

__device__ __forceinline__ void ldsm_x4(uint32_t r[4], uint32_t addr) {
    asm volatile("ldmatrix.sync.aligned.m8n8.x4.shared.b16 {%0,%1,%2,%3}, [%4];"
        : "=r"(r[0]), "=r"(r[1]), "=r"(r[2]), "=r"(r[3]) : "r"(addr));
}
__device__ __forceinline__ void mma_f16(float c[4], const uint32_t a[4],
                                        uint32_t b0, uint32_t b1) {
    asm volatile(
        "mma.sync.aligned.m16n8k16.row.col.f32.f16.f16.f32 "
        "{%0,%1,%2,%3}, {%4,%5,%6,%7}, {%8,%9}, {%0,%1,%2,%3};\n"
        : "+f"(c[0]), "+f"(c[1]), "+f"(c[2]), "+f"(c[3])
        : "r"(a[0]), "r"(a[1]), "r"(a[2]), "r"(a[3]), "r"(b0), "r"(b1));
}

// =====================================================================
// fp16 NT GEMM: C[m,n] = sum_k A[m,k] * W[n,k] + epilogue
// CTA 128x128, 256 threads (8 warps, warp = 32x64), K-chunk 64,
// 3-stage cp.async pipeline, ldmatrix, swizzled 128B smem rows.
// MODE 4: qkv single -> half2 channel-pair transposed store (out1)
// MODE 5: kv stacked -> n<256: out1 (k), n>=256: aux (v)
// MODE 0: proj -> +bias, fp32 store [m][CH]
// MODE 1: fc1  -> +bias, exact GELU, half store [m][HID]
// MODE 2: fc2  -> +bias +resid fp32 (aux), transposed fp32 store [B][C][H][W]
// =====================================================================
#define STAGE_B 32768   // 16KB A + 16KB B
#define SMEM_SZ (3*STAGE_B)

template<int MODE, int KDIM>
__global__ __launch_bounds__(256, 2)
void gemm_h(const __half* __restrict__ A, const __half* __restrict__ Wt,
            const float* __restrict__ bias, void* __restrict__ out1,
            void* __restrict__ aux)
{
    extern __shared__ __align__(128) char smem[];
    const uint32_t sb = smem_u32(smem);

    const int tid  = threadIdx.x;
    const int lane = tid & 31;
    const int wid  = tid >> 5;
    const int wm   = wid & 3;
    const int wn   = wid >> 2;
    const int lq   = lane >> 2;
    const int lr   = lane & 3;

    const int nT = blockIdx.x * 128;
    const int mT = blockIdx.y * 128;
    const int NCH = KDIM / 64;

    const int arow  = wm * 32 + (lane & 15);
    const int aqsel = lane >> 4;
    const uint32_t abase0 = (uint32_t)arow * 128;
    const uint32_t abase1 = (uint32_t)(arow + 16) * 128;
    const int axor = arow & 7;
    const int brow  = wn * 64 + (lane & 15);
    const int bqsel = lane >> 4;

    float acc[2][8][4];
    #pragma unroll
    for (int i = 0; i < 2; i++)
        #pragma unroll
        for (int j = 0; j < 8; j++)
            #pragma unroll
            for (int u = 0; u < 4; u++) acc[i][j][u] = 0.f;

    auto load_stage = [&](int s, int kt) {
        const uint32_t ab = sb + s * STAGE_B;
        const uint32_t bbm = ab + 16384;
        #pragma unroll
        for (int j = 0; j < 4; j++) {
            int c = tid + j * 256;
            int row = c >> 3, q = c & 7;
            uint32_t off = (uint32_t)row * 128 + (uint32_t)((q ^ (row & 7)) * 16);
            cp16(ab  + off, A  + (size_t)(mT + row) * KDIM + kt + q * 8);
            cp16(bbm + off, Wt + (size_t)(nT + row) * KDIM + kt + q * 8);
        }
    };

    load_stage(0, 0);  CP_COMMIT();
    if (NCH > 1) load_stage(1, 64);
    CP_COMMIT();
    if (NCH > 2) load_stage(2, 128);
    CP_COMMIT();

    for (int it = 0; it < NCH; it++) {
        const int s = it % 3;
        CP_WAIT2();
        __syncthreads();

        const uint32_t ab = sb + s * STAGE_B;
        const uint32_t bbm = ab + 16384;

        #pragma unroll
        for (int ks = 0; ks < 4; ks++) {
            const int q0 = ks * 2;
            uint32_t af[2][4];
            {
                const int qa = q0 + aqsel;
                ldsm_x4(af[0], ab + abase0 + (uint32_t)((qa ^ axor) * 16));
                ldsm_x4(af[1], ab + abase1 + (uint32_t)((qa ^ axor) * 16));
            }
            #pragma unroll
            for (int nt2 = 0; nt2 < 4; nt2++) {
                const int row = brow + nt2 * 16;
                const int qb = q0 + bqsel;
                uint32_t bf[4];
                ldsm_x4(bf, bbm + (uint32_t)row * 128 + (uint32_t)((qb ^ (row & 7)) * 16));
                mma_f16(acc[0][nt2*2  ], af[0], bf[0], bf[2]);
                mma_f16(acc[0][nt2*2+1], af[0], bf[1], bf[3]);
                mma_f16(acc[1][nt2*2  ], af[1], bf[0], bf[2]);
                mma_f16(acc[1][nt2*2+1], af[1], bf[1], bf[3]);
            }
        }
        __syncthreads();
        if (it + 3 < NCH) load_stage(s, (it + 3) * 64);
        CP_COMMIT();
    }

    // ---------------- epilogue ----------------
    #pragma unroll
    for (int mt = 0; mt < 2; mt++) {
        #pragma unroll
        for (int idx = 0; idx < 8; idx++) {
            const int nt2 = idx >> 1, tt = idx & 1;
            const int m0 = mT + wm * 32 + mt * 16 + lq;
            const int n0 = nT + wn * 64 + nt2 * 16 + tt * 8 + (lr << 1);
            const float* cc = acc[mt][idx];

            if (MODE == 4 || MODE == 5) {
                const int bi = m0 >> 12;
                const int hw = m0 & 4095;
                __half2* dst;
                int ch;
                if (MODE == 5) {
                    dst = (n0 < CH) ? (__half2*)out1 : (__half2*)aux;
                    ch = n0 & (CH - 1);
                } else { dst = (__half2*)out1; ch = n0; }
                __half2* p = dst + (size_t)bi * CP2 * HWSZ + (size_t)(ch >> 1) * HWSZ;
                p[hw    ] = __floats2half2_rn(cc[0], cc[1]);
                p[hw + 8] = __floats2half2_rn(cc[2], cc[3]);
            } else if (MODE == 0) {
                float* o = (float*)out1;
                float2 bv = *(const float2*)&bias[n0];
                *(float2*)&o[(size_t)m0 * CH + n0] =
                    make_float2(cc[0] + bv.x, cc[1] + bv.y);
                *(float2*)&o[(size_t)(m0 + 8) * CH + n0] =
                    make_float2(cc[2] + bv.x, cc[3] + bv.y);
            } else if (MODE == 1) {
                __half* o = (__half*)out1;
                float2 bv = *(const float2*)&bias[n0];
                float v[4] = {cc[0] + bv.x, cc[1] + bv.y, cc[2] + bv.x, cc[3] + bv.y};
                #pragma unroll
                for (int u = 0; u < 4; u++)
                    v[u] = 0.5f * v[u] * (1.f + erff(v[u] * 0.70710678118654752f));
                *(__half2*)&o[(size_t)m0 * HID + n0]       = __floats2half2_rn(v[0], v[1]);
                *(__half2*)&o[(size_t)(m0 + 8) * HID + n0] = __floats2half2_rn(v[2], v[3]);
            } else {
                float* o = (float*)out1;
                const float* resid = (const float*)aux;
                float2 bv = *(const float2*)&bias[n0];
                float2 r0 = *(const float2*)&resid[(size_t)m0 * CH + n0];
                float2 r1 = *(const float2*)&resid[(size_t)(m0 + 8) * CH + n0];
                const int bi = m0 >> 12;
                const int hw = m0 & 4095;
                float* p = o + (size_t)bi * CH * HWSZ;
                p[(size_t)(n0    ) * HWSZ + hw    ] = cc[0] + bv.x + r0.x;
                p[(size_t)(n0 + 1) * HWSZ + hw    ] = cc[1] + bv.y + r0.y;
                p[(size_t)(n0    ) * HWSZ + hw + 8] = cc[2] + bv.x + r1.x;
                p[(size_t)(n0 + 1) * HWSZ + hw + 8] = cc[3] + bv.y + r1.y;
            }
        }
    }
}

// =====================================================================
// Tiled transpose + fp16 cvt: [b][256][4096] fp32 -> [b*4096][256] fp16
// =====================================================================
__global__ void transpose_h(const float* __restrict__ in, __half* __restrict__ out)
{
    __shared__ float t[32][33];
    const int b  = blockIdx.z;
    const int p0 = blockIdx.x * 32;
    const int c0 = blockIdx.y * 32;
    const int tx = threadIdx.x, ty = threadIdx.y;   // 32 x 8
    const float* ib = in + (size_t)b * CH * HWSZ;
    __half* ob = out + (size_t)b * HWSZ * CH;
    #pragma unroll
    for (int i = 0; i < 4; i++)
        t[ty + 8*i][tx] = ib[(size_t)(c0 + ty + 8*i) * HWSZ + p0 + tx];
    __syncthreads();
    #pragma unroll
    for (int i = 0; i < 4; i++)
        ob[(size_t)(p0 + ty + 8*i) * CH + c0 + tx] = __float2half_rn(t[tx][ty + 8*i]);
}

// =====================================================================
// Dilated 3x3 local attention, branchless gathers (clamped idx + mask).
// fp16 channel-pair buffers, fp32 math. 1 thread = (pixel, head).
// =====================================================================
__global__ __launch_bounds__(128)
void attn_kernel(const __half2* __restrict__ q,
                 const __half2* __restrict__ k,
                 const __half2* __restrict__ v,
                 __half2* __restrict__ xo)
{
    const int b    = blockIdx.z;
    const int head = blockIdx.y;
    const int n    = blockIdx.x * 128 + threadIdx.x;
    const int py   = n >> 6;
    const int px   = n & 63;
    const int dil  = (head >> 1) + 1;

    const size_t base = ((size_t)b * CP2 + head * (HDIM/2)) * HWSZ;
    const __half2* qb = q + base + n;
    const __half2* kb = k + base;
    const __half2* vb = v + base;

    float2 qr[16];
    #pragma unroll
    for (int cp = 0; cp < 16; cp++) qr[cp] = __half22float2(qb[(size_t)cp * HWSZ]);

    int nn[9];
    float msk[9];
    #pragma unroll
    for (int t = 0; t < 9; t++) {
        int yy = py + (t / 3 - 1) * dil;
        int xx = px + (t % 3 - 1) * dil;
        const bool in = (yy >= 0 && yy < HH && xx >= 0 && xx < WW);
        nn[t] = in ? (yy * WW + xx) : n;
        msk[t] = in ? 1.f : 0.f;
    }

    float logit[9];
    #pragma unroll
    for (int t = 0; t < 9; t++) {
        float acc = 0.f;
        #pragma unroll
        for (int cp = 0; cp < 16; cp++) {
            float2 kv = __half22float2(kb[(size_t)cp * HWSZ + nn[t]]);
            acc += qr[cp].x * kv.x + qr[cp].y * kv.y;
        }
        logit[t] = acc * msk[t] * 0.17677669529663687f;
    }

    float mx = logit[0];
    #pragma unroll
    for (int t = 1; t < 9; t++) mx = fmaxf(mx, logit[t]);
    float s = 0.f;
    #pragma unroll
    for (int t = 0; t < 9; t++) { logit[t] = __expf(logit[t] - mx); s += logit[t]; }
    const float inv = 1.f / s;
    #pragma unroll
    for (int t = 0; t < 9; t++) logit[t] *= inv * msk[t];

    __half2* xrow = xo + (size_t)(b * HWSZ + n) * CP2 + head * (HDIM/2);
    #pragma unroll
    for (int cp = 0; cp < 16; cp++) {
        float ox = 0.f, oy = 0.f;
        #pragma unroll
        for (int t = 0; t < 9; t++) {
            float2 vv = __half22float2(vb[(size_t)cp * HWSZ + nn[t]]);
            ox += logit[t] * vv.x;
            oy += logit[t] * vv.y;
        }
        xrow[cp] = __floats2half2_rn(ox, oy);
    }
}

// =====================================================================
// LayerNorm over 256 channels: fp32 in (g_xp), fp16 out (g_ln).
// =====================================================================
__global__ void ln_kernel(const float* __restrict__ xp,
                          const float* __restrict__ w,
                          const float* __restrict__ bb,
                          __half2* __restrict__ out)
{
    const int warp = threadIdx.x >> 5;
    const int lane = threadIdx.x & 31;
    const int tok  = blockIdx.x * 8 + warp;
    const float* row = xp + (size_t)tok * CH;

    float4 v0 = *(const float4*)&row[lane * 8];
    float4 v1 = *(const float4*)&row[lane * 8 + 4];
    float va[8] = {v0.x, v0.y, v0.z, v0.w, v1.x, v1.y, v1.z, v1.w};

    float s = 0.f, sq = 0.f;
    #pragma unroll
    for (int u = 0; u < 8; u++) { s += va[u]; sq += va[u] * va[u]; }
    #pragma unroll
    for (int o = 16; o; o >>= 1) {
        s  += __shfl_xor_sync(0xffffffffu, s,  o);
        sq += __shfl_xor_sync(0xffffffffu, sq, o);
    }
    const float mean = s * (1.f / 256.f);
    const float var  = sq * (1.f / 256.f) - mean * mean;
    const float inv  = rsqrtf(var + 1e-5f);

    __half2* orow = out + (size_t)tok * CP2 + lane * 4;
    #pragma unroll
    for (int j = 0; j < 4; j++) {
        int ch = lane * 8 + j * 2;
        float a0 = (va[j*2]   - mean) * inv * w[ch]     + bb[ch];
        float a1 = (va[j*2+1] - mean) * inv * w[ch + 1] + bb[ch + 1];
        orow[j] = __floats2half2_rn(a0, a1);
    }
}

// =====================================================================
// Fused weight conversion: all six weights in one launch.
// Segments: wq 64K | wk 64K | wv 64K | wp 64K | w1 256K | w2 256K
// =====================================================================
__global__ void cvt_all(const float* __restrict__ wq, const float* __restrict__ wk,
                        const float* __restrict__ wv, const float* __restrict__ wp,
                        const float* __restrict__ w1, const float* __restrict__ w2,
                        __half* __restrict__ owq, __half* __restrict__ owkv,
                        __half* __restrict__ owp, __half* __restrict__ ow1,
                        __half* __restrict__ ow2)
{
    const int i = blockIdx.x * 256 + threadIdx.x;
    const int S = CH * CH;          // 65536
    if      (i <     S) owq [i        ] = __float2half_rn(wq[i]);
    else if (i < 2 * S) owkv[i - S    ] = __float2half_rn(wk[i - S]);
    else if (i < 3 * S) owkv[i - S    ] = __float2half_rn(wv[i - 2*S]);  // offset S into kv
    else if (i < 4 * S) owp [i - 3*S  ] = __float2half_rn(wp[i - 3*S]);
    else if (i < 8 * S) ow1 [i - 4*S  ] = __float2half_rn(w1[i - 4*S]);
    else                ow2 [i - 8*S  ] = __float2half_rn(w2[i - 8*S]);
}

// =====================================================================
extern "C" void kernel_launch(void* const* d_in, const int* in_sizes, int n_in,
                              void* d_out, int out_size)
{
    const float* sub    = (const float*)d_in[0];
    const float* ori    = (const float*)d_in[1];
    const float* wq     = (const float*)d_in[2];
    const float* wk     = (const float*)d_in[3];
    const float* wv     = (const float*)d_in[4];
    const float* proj_w = (const float*)d_in[5];
    const float* proj_b = (const float*)d_in[6];
    const float* ln_w   = (const float*)d_in[7];
    const float* ln_b   = (const float*)d_in[8];
    const float* fc1_w  = (const float*)d_in[9];
    const float* fc1_b  = (const float*)d_in[10];
    const float* fc2_w  = (const float*)d_in[11];
    const float* fc2_b  = (const float*)d_in[12];
    float* out = (float*)d_out;

    __half *p_ts, *p_to, *p_ln, *p_h, *p_wq, *p_wkv, *p_wp, *p_w1, *p_w2;
    __half2 *p_q, *p_k, *p_v, *p_x;
    float *p_xp;
    cudaGetSymbolAddress((void**)&p_ts,  g_ts);
    cudaGetSymbolAddress((void**)&p_to,  g_to);
    cudaGetSymbolAddress((void**)&p_q,   g_q);
    cudaGetSymbolAddress((void**)&p_k,   g_k);
    cudaGetSymbolAddress((void**)&p_v,   g_v);
    cudaGetSymbolAddress((void**)&p_x,   g_x);
    cudaGetSymbolAddress((void**)&p_xp,  g_xp);
    cudaGetSymbolAddress((void**)&p_ln,  g_ln);
    cudaGetSymbolAddress((void**)&p_h,   g_h);
    cudaGetSymbolAddress((void**)&p_wq,  g_wq);
    cudaGetSymbolAddress((void**)&p_wkv, g_wkv);
    cudaGetSymbolAddress((void**)&p_wp,  g_wp);
    cudaGetSymbolAddress((void**)&p_w1,  g_w1);
    cudaGetSymbolAddress((void**)&p_w2,  g_w2);

    cudaFuncSetAttribute(gemm_h<4, CH >, cudaFuncAttributeMaxDynamicSharedMemorySize, SMEM_SZ);
    cudaFuncSetAttribute(gemm_h<5, CH >, cudaFuncAttributeMaxDynamicSharedMemorySize, SMEM_SZ);
    cudaFuncSetAttribute(gemm_h<0, CH >, cudaFuncAttributeMaxDynamicSharedMemorySize, SMEM_SZ);
    cudaFuncSetAttribute(gemm_h<1, CH >, cudaFuncAttributeMaxDynamicSharedMemorySize, SMEM_SZ);
    cudaFuncSetAttribute(gemm_h<2, HID>, cudaFuncAttributeMaxDynamicSharedMemorySize, SMEM_SZ);

    // 0: all weight conversions (wv lands at g_wkv + CH*CH via index math)
    cvt_all<<<(12 * CH * CH) / 256, 256>>>(wq, wk, wv, proj_w, fc1_w, fc2_w,
                                           p_wq, p_wkv, p_wp, p_w1, p_w2);

    // 1,2: transpose inputs to [tok][c] fp16
    dim3 gt(HWSZ / 32, CH / 32, BATCH);
    dim3 bt(32, 8);
    transpose_h<<<gt, bt>>>(sub, p_ts);
    transpose_h<<<gt, bt>>>(ori, p_to);

    // 3: q GEMM   4: stacked k|v GEMM   5: attention  (ncu sample slot ~4-5)
    dim3 gq(CH / 128, NTOK / 128);
    gemm_h<4, CH><<<gq, 256, SMEM_SZ>>>(p_ts, p_wq, nullptr, p_q, nullptr);
    dim3 gkv(2 * CH / 128, NTOK / 128);
    gemm_h<5, CH><<<gkv, 256, SMEM_SZ>>>(p_to, p_wkv, nullptr, p_k, p_v);
    dim3 ga(HWSZ / 128, NHEAD, BATCH);
    attn_kernel<<<ga, 128>>>(p_q, p_k, p_v, p_x);

    // proj + bias -> g_xp fp32
    dim3 gp(CH / 128, NTOK / 128);
    gemm_h<0, CH><<<gp, 256, SMEM_SZ>>>((const __half*)p_x, p_wp, proj_b, p_xp, nullptr);

    // layernorm -> g_ln fp16
    ln_kernel<<<NTOK / 8, 256>>>(p_xp, ln_w, ln_b, (__half2*)p_ln);

    // fc1 + bias + GELU -> g_h fp16
    dim3 g1(HID / 128, NTOK / 128);
    gemm_h<1, CH><<<g1, 256, SMEM_SZ>>>(p_ln, p_w1, fc1_b, p_h, nullptr);

    // fc2 + bias + residual, transposed fp32 store -> d_out [B][C][H][W]
    dim3 g2(CH / 128, NTOK / 128);
    gemm_h<2, HID><<<g2, 256, SMEM_SZ>>>(p_h, p_w2, fc2_b, out, p_xp);
}